// round 5
// baseline (speedup 1.0000x reference)
#include <cuda_runtime.h>
#include <cuda_fp16.h>
#include <cstdint>

// Fused LSTM cell, sm_103 family-generic (no tcgen05 in this toolchain).
// Pass 1: fp32 -> fp16(rn) once.  AscrH = [x|h] (32768 x 1024 row-major).
//         BscrH = [Wx;Wh]^T gate-permuted: [N'=2048][K=1024], where
//         n' = nt*256 + g*64 + j  <->  weight col g*512 + nt*64 + j.
// Pass 2: 128x256x1024 GEMM per CTA (warp tile 64x64), cp.async 3-stage,
//         ldmatrix.x4 fragments, mma.sync.m16n8k16.f16 (fp32 accum),
//         fused LSTM gate epilogue. 1 CTA/SM, 8 warps.

#define BATCH 32768
#define DH 512
#define KTOT 1024
#define NTOT 2048

#define BM 128
#define BN 256
#define BK 64
#define KTILES (KTOT / BK)  // 16
#define STAGES 3
#define THREADS 256

#define ROWP 72                         // halves per smem row (64 + 8 pad)
#define A_TILE_B (BM * ROWP * 2)        // 18432 B
#define B_TILE_B (BN * ROWP * 2)        // 36864 B
#define STG_BYTES (A_TILE_B + B_TILE_B) // 55296 B
#define SMEM_BYTES (STAGES * STG_BYTES) // 165888 B
#define LDZ 260
// epilogue zs reuse: 128*260*4 = 133120 <= 165888 ok

// ---------------- device scratch ----------------
__device__ __half AscrH[(size_t)BATCH * KTOT];  // 64 MB
__device__ __half BscrH[(size_t)NTOT * KTOT];   // 4 MB

__device__ __forceinline__ uint32_t smem_u32(const void* p) {
    uint32_t a;
    asm("{ .reg .u64 t; cvta.to.shared.u64 t, %1; cvt.u32.u64 %0, t; }"
        : "=r"(a) : "l"(p));
    return a;
}
__device__ __forceinline__ void cp16(uint32_t sm, const void* g) {
    asm volatile("cp.async.cg.shared.global [%0], [%1], 16;"
                 :: "r"(sm), "l"(g) : "memory");
}
__device__ __forceinline__ void ldsm_x4(uint32_t& r0, uint32_t& r1,
                                        uint32_t& r2, uint32_t& r3,
                                        uint32_t addr) {
    asm volatile("ldmatrix.sync.aligned.m8n8.x4.shared.b16 {%0,%1,%2,%3}, [%4];"
                 : "=r"(r0), "=r"(r1), "=r"(r2), "=r"(r3) : "r"(addr));
}
__device__ __forceinline__ void mma_f16(float d[4], const uint32_t a[4],
                                        const uint32_t b[2], const float c[4]) {
    asm volatile(
        "mma.sync.aligned.m16n8k16.row.col.f32.f16.f16.f32 "
        "{%0,%1,%2,%3}, {%4,%5,%6,%7}, {%8,%9}, {%10,%11,%12,%13};\n"
        : "=f"(d[0]), "=f"(d[1]), "=f"(d[2]), "=f"(d[3])
        : "r"(a[0]), "r"(a[1]), "r"(a[2]), "r"(a[3]),
          "r"(b[0]), "r"(b[1]),
          "f"(c[0]), "f"(c[1]), "f"(c[2]), "f"(c[3]));
}

__device__ __forceinline__ float sigm(float v) { return 1.0f / (1.0f + __expf(-v)); }
__device__ __forceinline__ float tanh_fast(float v) {
    return 2.0f / (1.0f + __expf(-2.0f * v)) - 1.0f;
}

// ---------------- pass 1 ----------------
__global__ void __launch_bounds__(256) prep_a(const float* __restrict__ x,
                                              const float* __restrict__ h) {
    size_t i = (size_t)blockIdx.x * 256 + threadIdx.x;  // float4 index
    size_t e = i * 4;
    int b = (int)(e >> 10);
    int k = (int)(e & 1023);
    const float* src = (k < 512) ? (x + (size_t)b * 512 + k)
                                 : (h + (size_t)b * 512 + (k - 512));
    float4 v = *(const float4*)src;
    __half2 h0 = __floats2half2_rn(v.x, v.y);
    __half2 h1 = __floats2half2_rn(v.z, v.w);
    uint2 o = make_uint2(*(uint32_t*)&h0, *(uint32_t*)&h1);
    *(uint2*)(AscrH + e) = o;
}

// BscrH[n'][k] = W[k][col(n')], n' = nt*256 + g*64 + j, col = g*512 + nt*64 + j
__global__ void __launch_bounds__(256) prep_b(const float* __restrict__ Wx,
                                              const float* __restrict__ Wh) {
    size_t t = (size_t)blockIdx.x * 256 + threadIdx.x;  // 524288 threads
    int np = (int)(t >> 8);          // n' 0..2047
    int kb = (int)(t & 255) * 4;     // k base
    int nt = np >> 8;
    int g = (np >> 6) & 3;
    int j = np & 63;
    int col = g * 512 + nt * 64 + j;
    const float* src = (kb < 512) ? (Wx + (size_t)kb * NTOT + col)
                                  : (Wh + (size_t)(kb - 512) * NTOT + col);
    float v0 = src[0];
    float v1 = src[NTOT];
    float v2 = src[2 * NTOT];
    float v3 = src[3 * NTOT];
    __half2 h0 = __floats2half2_rn(v0, v1);
    __half2 h1 = __floats2half2_rn(v2, v3);
    uint2 o = make_uint2(*(uint32_t*)&h0, *(uint32_t*)&h1);
    *(uint2*)(BscrH + (size_t)np * KTOT + kb) = o;
}

// ---------------- pass 2 ----------------
__global__ void __launch_bounds__(THREADS, 1)
lstm_gemm(const float* __restrict__ Cin, const float* __restrict__ bx,
          const float* __restrict__ bh, float* __restrict__ out) {
    extern __shared__ float smem[];
    const uint32_t sbase = smem_u32(smem);

    const int tid = threadIdx.x;
    const int warp = tid >> 5;
    const int lane = tid & 31;
    const int wm = warp & 1;   // 2 warps along M (64 rows each)
    const int wn = warp >> 1;  // 4 warps along N (64 cols each)
    const int gid = lane >> 2;
    const int tig = lane & 3;

    const int mBase = blockIdx.y * BM;
    const int nt = blockIdx.x;

    float acc[4][8][4];
#pragma unroll
    for (int mt = 0; mt < 4; ++mt)
#pragma unroll
        for (int n = 0; n < 8; ++n)
#pragma unroll
            for (int c = 0; c < 4; ++c) acc[mt][n][c] = 0.0f;

    // cp.async coordinates: 16B chunk = tid + i*256; row = chunk>>3, c = chunk&7
    const int ldR = tid >> 3;   // 0..31, +32 per i
    const int ldC = tid & 7;

    const __half* gA0 = AscrH + (size_t)(mBase + ldR) * KTOT + ldC * 8;
    const __half* gB0 = BscrH + (size_t)(nt * BN + ldR) * KTOT + ldC * 8;

    auto issue = [&](int kt) {
        const int s = kt % STAGES;
        const uint32_t sa = sbase + (uint32_t)s * STG_BYTES;
        const uint32_t sb = sa + A_TILE_B;
        const uint32_t soff = (uint32_t)(ldR * ROWP + ldC * 8) * 2;
        const size_t kg = (size_t)kt * BK;
#pragma unroll
        for (int i = 0; i < 4; ++i)
            cp16(sa + soff + i * 32 * ROWP * 2, gA0 + kg + (size_t)i * 32 * KTOT);
#pragma unroll
        for (int i = 0; i < 8; ++i)
            cp16(sb + soff + i * 32 * ROWP * 2, gB0 + kg + (size_t)i * 32 * KTOT);
        asm volatile("cp.async.commit_group;" ::: "memory");
    };

    // ldmatrix lane offset (bytes): rows (lane&15), k-half (lane>>4)*8 halves
    const uint32_t lmOff = (uint32_t)((lane & 15) * ROWP + (lane >> 4) * 8) * 2;
    const uint32_t aWarp = (uint32_t)(wm * 64 * ROWP) * 2 + lmOff;
    const uint32_t bWarp = (uint32_t)(wn * 64 * ROWP) * 2 + lmOff;

    auto compute = [&](int s) {
        const uint32_t sa = sbase + (uint32_t)s * STG_BYTES;
        const uint32_t sb = sa + A_TILE_B;
#pragma unroll
        for (int ks = 0; ks < 4; ++ks) {
            const uint32_t kOff = ks * 32;  // 16 halves
            uint32_t a[4][4];
#pragma unroll
            for (int mt = 0; mt < 4; ++mt)
                ldsm_x4(a[mt][0], a[mt][1], a[mt][2], a[mt][3],
                        sa + aWarp + (uint32_t)(mt * 16 * ROWP) * 2 + kOff);
            uint32_t bf[8][2];
#pragma unroll
            for (int p = 0; p < 4; ++p) {
                uint32_t r0, r1, r2, r3;
                ldsm_x4(r0, r1, r2, r3,
                        sb + bWarp + (uint32_t)(p * 16 * ROWP) * 2 + kOff);
                bf[2 * p][0] = r0;     bf[2 * p][1] = r2;
                bf[2 * p + 1][0] = r1; bf[2 * p + 1][1] = r3;
            }
#pragma unroll
            for (int mt = 0; mt < 4; ++mt)
#pragma unroll
                for (int n = 0; n < 8; ++n)
                    mma_f16(acc[mt][n], a[mt], bf[n], acc[mt][n]);
        }
    };

    issue(0);
    issue(1);

#pragma unroll 1
    for (int kt = 0; kt < KTILES; ++kt) {
        if (kt == KTILES - 1) {
            asm volatile("cp.async.wait_group 0;" ::: "memory");
        } else {
            asm volatile("cp.async.wait_group 1;" ::: "memory");
        }
        __syncthreads();
        if (kt + STAGES - 1 < KTILES) issue(kt + STAGES - 1);
        compute(kt % STAGES);
    }

    // ---------------- epilogue ----------------
    __syncthreads();
    float* zs = smem;
#pragma unroll
    for (int mt = 0; mt < 4; ++mt)
#pragma unroll
        for (int n = 0; n < 8; ++n)
#pragma unroll
            for (int c = 0; c < 4; ++c) {
                const int r = wm * 64 + mt * 16 + gid + ((c >= 2) ? 8 : 0);
                const int cc = wn * 64 + n * 8 + tig * 2 + (c & 1);
                zs[r * LDZ + cc] = acc[mt][n][c];
            }
    __syncthreads();

    float* outH = out + (size_t)BATCH * DH;
#pragma unroll 1
    for (int i = 0; i < 32; ++i) {
        const int idx = tid + i * THREADS;  // 0..8191
        const int m = idx >> 6;             // 0..127
        const int j = idx & 63;             // 0..63
        const int hj = nt * 64 + j;
        const float zi = zs[m * LDZ + j]       + __ldg(bx + hj)        + __ldg(bh + hj);
        const float zf = zs[m * LDZ + 64 + j]  + __ldg(bx + 512 + hj)  + __ldg(bh + 512 + hj);
        const float zo = zs[m * LDZ + 128 + j] + __ldg(bx + 1024 + hj) + __ldg(bh + 1024 + hj);
        const float zg = zs[m * LDZ + 192 + j] + __ldg(bx + 1536 + hj) + __ldg(bh + 1536 + hj);
        const float ig = sigm(zi);
        const float fg = sigm(zf);
        const float og = sigm(zo);
        const float gg = tanh_fast(zg);
        const size_t goff = (size_t)(mBase + m) * DH + hj;
        const float cnew = fg * Cin[goff] + ig * gg;
        out[goff] = cnew;
        outH[goff] = og * tanh_fast(cnew);
    }
}

extern "C" void kernel_launch(void* const* d_in, const int* in_sizes, int n_in,
                              void* d_out, int out_size) {
    const float* x = (const float*)d_in[0];
    const float* C = (const float*)d_in[1];
    const float* h = (const float*)d_in[2];
    const float* Wx = (const float*)d_in[3];
    const float* bx = (const float*)d_in[4];
    const float* Wh = (const float*)d_in[5];
    const float* bh = (const float*)d_in[6];
    float* out = (float*)d_out;

    cudaFuncSetAttribute(lstm_gemm, cudaFuncAttributeMaxDynamicSharedMemorySize,
                         SMEM_BYTES);

    prep_a<<<(size_t)BATCH * KTOT / 4 / 256, 256>>>(x, h);
    prep_b<<<(size_t)NTOT * KTOT / 4 / 256, 256>>>(Wx, Wh);
    dim3 grid(NTOT / BN, BATCH / BM);  // (8, 256)
    lstm_gemm<<<grid, THREADS, SMEM_BYTES>>>(C, bx, bh, out);
}

// round 6
// speedup vs baseline: 1.0381x; 1.0381x over previous
#include <cuda_runtime.h>
#include <cuda_fp16.h>
#include <cstdint>

// Fused LSTM cell, sm_103 family-generic (no tcgen05 in this toolchain).
// Pass 1: fp32 -> fp16(rn) once.  AscrH = [x|h] (32768 x 1024 row-major).
//         BscrH = [Wx;Wh]^T gate-permuted: [N'=2048][K=1024], where
//         n' = nt*128 + g*32 + j  <->  weight col g*512 + nt*32 + j.
// Pass 2: 128x128x1024 GEMM per CTA, 128 threads (4 warps, warp tile 64x64),
//         cp.async 3-stage pipeline, ldmatrix.x4, mma.sync.m16n8k16.f16,
//         fused LSTM gate epilogue. 2 CTAs/SM.

#define BATCH 32768
#define DH 512
#define KTOT 1024
#define NTOT 2048

#define BM 128
#define BN 128
#define BK 64
#define KTILES (KTOT / BK)  // 16
#define STAGES 3
#define THREADS 128

#define ROWP 72                       // halves per smem row (64 + 8 pad)
#define TILE_H (128 * ROWP)           // 9216 halves per A/B tile
#define STG_BYTES (2 * TILE_H * 2)    // 36864 B
#define SMEM_BYTES (STAGES * STG_BYTES)  // 110592
#define LDZ 132
// epilogue zs reuse: 128*132*4 = 67584 <= 110592 ok

// ---------------- device scratch ----------------
__device__ __half AscrH[(size_t)BATCH * KTOT];  // 64 MB
__device__ __half BscrH[(size_t)NTOT * KTOT];   // 4 MB

__device__ __forceinline__ uint32_t smem_u32(const void* p) {
    uint32_t a;
    asm("{ .reg .u64 t; cvta.to.shared.u64 t, %1; cvt.u32.u64 %0, t; }"
        : "=r"(a) : "l"(p));
    return a;
}
__device__ __forceinline__ void cp16(uint32_t sm, const void* g) {
    asm volatile("cp.async.cg.shared.global [%0], [%1], 16;"
                 :: "r"(sm), "l"(g) : "memory");
}
__device__ __forceinline__ void ldsm_x4(uint32_t& r0, uint32_t& r1,
                                        uint32_t& r2, uint32_t& r3,
                                        uint32_t addr) {
    asm volatile("ldmatrix.sync.aligned.m8n8.x4.shared.b16 {%0,%1,%2,%3}, [%4];"
                 : "=r"(r0), "=r"(r1), "=r"(r2), "=r"(r3) : "r"(addr));
}
__device__ __forceinline__ void mma_f16(float d[4], const uint32_t a[4],
                                        const uint32_t b[2], const float c[4]) {
    asm volatile(
        "mma.sync.aligned.m16n8k16.row.col.f32.f16.f16.f32 "
        "{%0,%1,%2,%3}, {%4,%5,%6,%7}, {%8,%9}, {%10,%11,%12,%13};\n"
        : "=f"(d[0]), "=f"(d[1]), "=f"(d[2]), "=f"(d[3])
        : "r"(a[0]), "r"(a[1]), "r"(a[2]), "r"(a[3]),
          "r"(b[0]), "r"(b[1]),
          "f"(c[0]), "f"(c[1]), "f"(c[2]), "f"(c[3]));
}

__device__ __forceinline__ float sigm(float v) { return 1.0f / (1.0f + __expf(-v)); }
__device__ __forceinline__ float tanh_fast(float v) {
    return 2.0f / (1.0f + __expf(-2.0f * v)) - 1.0f;
}

// ---------------- pass 1 ----------------
__global__ void __launch_bounds__(256) prep_a(const float* __restrict__ x,
                                              const float* __restrict__ h) {
    size_t i = (size_t)blockIdx.x * 256 + threadIdx.x;  // float4 index
    size_t e = i * 4;
    int b = (int)(e >> 10);
    int k = (int)(e & 1023);
    const float* src = (k < 512) ? (x + (size_t)b * 512 + k)
                                 : (h + (size_t)b * 512 + (k - 512));
    float4 v = *(const float4*)src;
    __half2 h0 = __floats2half2_rn(v.x, v.y);
    __half2 h1 = __floats2half2_rn(v.z, v.w);
    uint2 o = make_uint2(*(uint32_t*)&h0, *(uint32_t*)&h1);
    *(uint2*)(AscrH + e) = o;
}

// BscrH[n'][k] = W[k][col(n')],  n' = nt*128 + g*32 + j, col = g*512 + nt*32 + j
__global__ void __launch_bounds__(256) prep_b(const float* __restrict__ Wx,
                                              const float* __restrict__ Wh) {
    size_t t = (size_t)blockIdx.x * 256 + threadIdx.x;  // 524288 threads
    int np = (int)(t >> 8);          // n' 0..2047
    int kb = (int)(t & 255) * 4;     // k base
    int nt = np >> 7;
    int g = (np >> 5) & 3;
    int j = np & 31;
    int col = g * 512 + nt * 32 + j;
    const float* src = (kb < 512) ? (Wx + (size_t)kb * NTOT + col)
                                  : (Wh + (size_t)(kb - 512) * NTOT + col);
    float v0 = src[0];
    float v1 = src[NTOT];
    float v2 = src[2 * NTOT];
    float v3 = src[3 * NTOT];
    __half2 h0 = __floats2half2_rn(v0, v1);
    __half2 h1 = __floats2half2_rn(v2, v3);
    uint2 o = make_uint2(*(uint32_t*)&h0, *(uint32_t*)&h1);
    *(uint2*)(BscrH + (size_t)np * KTOT + kb) = o;
}

// ---------------- pass 2 ----------------
__global__ void __launch_bounds__(THREADS, 2)
lstm_gemm(const float* __restrict__ Cin, const float* __restrict__ bx,
          const float* __restrict__ bh, float* __restrict__ out) {
    extern __shared__ float smem[];
    const uint32_t sbase = smem_u32(smem);

    const int tid = threadIdx.x;
    const int warp = tid >> 5;
    const int lane = tid & 31;
    const int wm = warp & 1;   // 2 warps along M (64 rows each)
    const int wn = warp >> 1;  // 2 warps along N (64 cols each)
    const int gid = lane >> 2;
    const int tig = lane & 3;

    const int mBase = blockIdx.y * BM;
    const int nt = blockIdx.x;

    float acc[4][8][4];
#pragma unroll
    for (int mt = 0; mt < 4; ++mt)
#pragma unroll
        for (int n = 0; n < 8; ++n)
#pragma unroll
            for (int c = 0; c < 4; ++c) acc[mt][n][c] = 0.0f;

    // cp.async coordinates: 16B chunk = tid + i*128; row = chunk>>3, c = chunk&7
    const int ldR = tid >> 3;   // 0..15, +16 per i
    const int ldC = tid & 7;

    const __half* gA0 = AscrH + (size_t)(mBase + ldR) * KTOT + ldC * 8;
    const __half* gB0 = BscrH + (size_t)(nt * BN + ldR) * KTOT + ldC * 8;

    auto issue = [&](int kt) {
        const int s = kt % STAGES;
        const uint32_t sa = sbase + (uint32_t)s * STG_BYTES;
        const uint32_t sb = sa + TILE_H * 2;
        const uint32_t soff = (uint32_t)(ldR * ROWP + ldC * 8) * 2;
        const size_t kg = (size_t)kt * BK;
#pragma unroll
        for (int i = 0; i < 8; ++i) {
            cp16(sa + soff + i * 16 * ROWP * 2, gA0 + kg + (size_t)i * 16 * KTOT);
            cp16(sb + soff + i * 16 * ROWP * 2, gB0 + kg + (size_t)i * 16 * KTOT);
        }
        asm volatile("cp.async.commit_group;" ::: "memory");
    };

    // ldmatrix lane offset (bytes): rows (lane&15), k-half (lane>>4)*8 halves
    const uint32_t lmOff = (uint32_t)((lane & 15) * ROWP + (lane >> 4) * 8) * 2;
    const uint32_t aWarp = (uint32_t)(wm * 64 * ROWP) * 2 + lmOff;
    const uint32_t bWarp = (uint32_t)(wn * 64 * ROWP) * 2 + lmOff;

    auto compute = [&](int s) {
        const uint32_t sa = sbase + (uint32_t)s * STG_BYTES;
        const uint32_t sb = sa + TILE_H * 2;
#pragma unroll
        for (int ks = 0; ks < 4; ++ks) {
            const uint32_t kOff = ks * 32;  // 16 halves
            uint32_t a[4][4];
#pragma unroll
            for (int mt = 0; mt < 4; ++mt)
                ldsm_x4(a[mt][0], a[mt][1], a[mt][2], a[mt][3],
                        sa + aWarp + (uint32_t)(mt * 16 * ROWP) * 2 + kOff);
            uint32_t bf[8][2];
#pragma unroll
            for (int p = 0; p < 4; ++p) {
                uint32_t r0, r1, r2, r3;
                ldsm_x4(r0, r1, r2, r3,
                        sb + bWarp + (uint32_t)(p * 16 * ROWP) * 2 + kOff);
                bf[2 * p][0] = r0;     bf[2 * p][1] = r2;
                bf[2 * p + 1][0] = r1; bf[2 * p + 1][1] = r3;
            }
#pragma unroll
            for (int mt = 0; mt < 4; ++mt)
#pragma unroll
                for (int n = 0; n < 8; ++n)
                    mma_f16(acc[mt][n], a[mt], bf[n], acc[mt][n]);
        }
    };

    issue(0);
    issue(1);

#pragma unroll 1
    for (int kt = 0; kt < KTILES; ++kt) {
        if (kt == KTILES - 1) {
            asm volatile("cp.async.wait_group 0;" ::: "memory");
        } else {
            asm volatile("cp.async.wait_group 1;" ::: "memory");
        }
        __syncthreads();
        if (kt + STAGES - 1 < KTILES) issue(kt + STAGES - 1);
        compute(kt % STAGES);
    }

    // ---------------- epilogue ----------------
    __syncthreads();
    float* zs = smem;
#pragma unroll
    for (int mt = 0; mt < 4; ++mt)
#pragma unroll
        for (int n = 0; n < 8; ++n)
#pragma unroll
            for (int c = 0; c < 4; ++c) {
                const int r = wm * 64 + mt * 16 + gid + ((c >= 2) ? 8 : 0);
                const int cc = wn * 64 + n * 8 + tig * 2 + (c & 1);
                zs[r * LDZ + cc] = acc[mt][n][c];
            }
    __syncthreads();

    float* outH = out + (size_t)BATCH * DH;
#pragma unroll 1
    for (int i = 0; i < 32; ++i) {
        const int idx = tid + i * THREADS;  // 0..4095
        const int m = idx >> 5;             // 0..127
        const int j = idx & 31;             // 0..31
        const int hj = nt * 32 + j;
        const float zi = zs[m * LDZ + j]      + __ldg(bx + hj)        + __ldg(bh + hj);
        const float zf = zs[m * LDZ + 32 + j] + __ldg(bx + 512 + hj)  + __ldg(bh + 512 + hj);
        const float zo = zs[m * LDZ + 64 + j] + __ldg(bx + 1024 + hj) + __ldg(bh + 1024 + hj);
        const float zg = zs[m * LDZ + 96 + j] + __ldg(bx + 1536 + hj) + __ldg(bh + 1536 + hj);
        const float ig = sigm(zi);
        const float fg = sigm(zf);
        const float og = sigm(zo);
        const float gg = tanh_fast(zg);
        const size_t goff = (size_t)(mBase + m) * DH + hj;
        const float cnew = fg * Cin[goff] + ig * gg;
        out[goff] = cnew;
        outH[goff] = og * tanh_fast(cnew);
    }
}

extern "C" void kernel_launch(void* const* d_in, const int* in_sizes, int n_in,
                              void* d_out, int out_size) {
    const float* x = (const float*)d_in[0];
    const float* C = (const float*)d_in[1];
    const float* h = (const float*)d_in[2];
    const float* Wx = (const float*)d_in[3];
    const float* bx = (const float*)d_in[4];
    const float* Wh = (const float*)d_in[5];
    const float* bh = (const float*)d_in[6];
    float* out = (float*)d_out;

    cudaFuncSetAttribute(lstm_gemm, cudaFuncAttributeMaxDynamicSharedMemorySize,
                         SMEM_BYTES);

    prep_a<<<(size_t)BATCH * KTOT / 4 / 256, 256>>>(x, h);
    prep_b<<<(size_t)NTOT * KTOT / 4 / 256, 256>>>(Wx, Wh);
    dim3 grid(NTOT / BN, BATCH / BM);  // (16, 256)
    lstm_gemm<<<grid, THREADS, SMEM_BYTES>>>(C, bx, bh, out);
}

// round 7
// speedup vs baseline: 1.5216x; 1.4658x over previous
#include <cuda_runtime.h>
#include <cuda_fp16.h>
#include <cstdint>

// Fused LSTM cell, sm_103 family-generic (no tcgen05 in this toolchain).
// Pass 1 (single kernel): fp32 -> fp16(rn):
//   AscrH = [x|h] (32768 x 1024 row-major)
//   BscrH = [Wx;Wh]^T gate-permuted [N'=2048][K=1024],
//           n' = nt*128 + g*32 + j <-> weight col g*512 + nt*32 + j.
// Pass 2: 128x128x1024 GEMM per CTA, 256 threads (8 warps, warp tile 32x64),
//   cp.async 3-stage pipeline, interleaved ldmatrix.x4 + mma.sync.m16n8k16,
//   fused LSTM gate epilogue. 2 CTAs/SM (16 warps/SM).

#define BATCH 32768
#define DH 512
#define KTOT 1024
#define NTOT 2048

#define BM 128
#define BN 128
#define BK 64
#define KTILES (KTOT / BK)  // 16
#define STAGES 3
#define THREADS 256

#define ROWP 72                       // halves per smem row (64 + 8 pad)
#define TILE_H (128 * ROWP)           // 9216 halves per A/B tile
#define STG_BYTES (2 * TILE_H * 2)    // 36864 B
#define SMEM_BYTES (STAGES * STG_BYTES)  // 110592
#define LDZ 132
// epilogue zs reuse: 128*132*4 = 67584 <= 110592 ok

#define PREP_A_BLOCKS 32768           // 8,388,608 float4 / 256
#define PREP_B_BLOCKS 2048            // 524,288 items / 256

// ---------------- device scratch ----------------
__device__ __half AscrH[(size_t)BATCH * KTOT];  // 64 MB
__device__ __half BscrH[(size_t)NTOT * KTOT];   // 4 MB

__device__ __forceinline__ uint32_t smem_u32(const void* p) {
    uint32_t a;
    asm("{ .reg .u64 t; cvta.to.shared.u64 t, %1; cvt.u32.u64 %0, t; }"
        : "=r"(a) : "l"(p));
    return a;
}
__device__ __forceinline__ void cp16(uint32_t sm, const void* g) {
    asm volatile("cp.async.cg.shared.global [%0], [%1], 16;"
                 :: "r"(sm), "l"(g) : "memory");
}
__device__ __forceinline__ void ldsm_x4(uint32_t& r0, uint32_t& r1,
                                        uint32_t& r2, uint32_t& r3,
                                        uint32_t addr) {
    asm volatile("ldmatrix.sync.aligned.m8n8.x4.shared.b16 {%0,%1,%2,%3}, [%4];"
                 : "=r"(r0), "=r"(r1), "=r"(r2), "=r"(r3) : "r"(addr));
}
__device__ __forceinline__ void mma_f16(float d[4], const uint32_t a[4],
                                        const uint32_t b0, const uint32_t b1,
                                        const float c[4]) {
    asm volatile(
        "mma.sync.aligned.m16n8k16.row.col.f32.f16.f16.f32 "
        "{%0,%1,%2,%3}, {%4,%5,%6,%7}, {%8,%9}, {%10,%11,%12,%13};\n"
        : "=f"(d[0]), "=f"(d[1]), "=f"(d[2]), "=f"(d[3])
        : "r"(a[0]), "r"(a[1]), "r"(a[2]), "r"(a[3]),
          "r"(b0), "r"(b1),
          "f"(c[0]), "f"(c[1]), "f"(c[2]), "f"(c[3]));
}

__device__ __forceinline__ float sigm(float v) { return 1.0f / (1.0f + __expf(-v)); }
__device__ __forceinline__ float tanh_fast(float v) {
    return 2.0f / (1.0f + __expf(-2.0f * v)) - 1.0f;
}

// ---------------- pass 1: merged conversion ----------------
__global__ void __launch_bounds__(256) prep_all(const float* __restrict__ x,
                                                const float* __restrict__ h,
                                                const float* __restrict__ Wx,
                                                const float* __restrict__ Wh) {
    if (blockIdx.x < PREP_A_BLOCKS) {
        size_t i = (size_t)blockIdx.x * 256 + threadIdx.x;  // float4 index
        size_t e = i * 4;
        int b = (int)(e >> 10);
        int k = (int)(e & 1023);
        const float* src = (k < 512) ? (x + (size_t)b * 512 + k)
                                     : (h + (size_t)b * 512 + (k - 512));
        float4 v = *(const float4*)src;
        __half2 h0 = __floats2half2_rn(v.x, v.y);
        __half2 h1 = __floats2half2_rn(v.z, v.w);
        uint2 o = make_uint2(*(uint32_t*)&h0, *(uint32_t*)&h1);
        *(uint2*)(AscrH + e) = o;
    } else {
        // BscrH[n'][k] = W[k][col], n' = nt*128+g*32+j, col = g*512+nt*32+j
        size_t t = (size_t)(blockIdx.x - PREP_A_BLOCKS) * 256 + threadIdx.x;
        int np = (int)(t >> 8);          // n' 0..2047
        int kb = (int)(t & 255) * 4;     // k base
        int nt = np >> 7;
        int g = (np >> 5) & 3;
        int j = np & 31;
        int col = g * 512 + nt * 32 + j;
        const float* src = (kb < 512) ? (Wx + (size_t)kb * NTOT + col)
                                      : (Wh + (size_t)(kb - 512) * NTOT + col);
        float v0 = src[0];
        float v1 = src[NTOT];
        float v2 = src[2 * NTOT];
        float v3 = src[3 * NTOT];
        __half2 h0 = __floats2half2_rn(v0, v1);
        __half2 h1 = __floats2half2_rn(v2, v3);
        uint2 o = make_uint2(*(uint32_t*)&h0, *(uint32_t*)&h1);
        *(uint2*)(BscrH + (size_t)np * KTOT + kb) = o;
    }
}

// ---------------- pass 2 ----------------
__global__ void __launch_bounds__(THREADS, 2)
lstm_gemm(const float* __restrict__ Cin, const float* __restrict__ bx,
          const float* __restrict__ bh, float* __restrict__ out) {
    extern __shared__ float smem[];
    const uint32_t sbase = smem_u32(smem);

    const int tid = threadIdx.x;
    const int warp = tid >> 5;
    const int lane = tid & 31;
    const int wm = warp & 3;   // 4 warps along M (32 rows each)
    const int wn = warp >> 2;  // 2 warps along N (64 cols each)
    const int gid = lane >> 2;
    const int tig = lane & 3;

    const int mBase = blockIdx.y * BM;
    const int nt = blockIdx.x;

    float acc[2][8][4];
#pragma unroll
    for (int mt = 0; mt < 2; ++mt)
#pragma unroll
        for (int n = 0; n < 8; ++n)
#pragma unroll
            for (int c = 0; c < 4; ++c) acc[mt][n][c] = 0.0f;

    // cp.async coordinates: 16B chunk = tid + i*256; row = chunk>>3, c = chunk&7
    const int ldR = tid >> 3;   // 0..31, +32 per i
    const int ldC = tid & 7;

    const __half* gA0 = AscrH + (size_t)(mBase + ldR) * KTOT + ldC * 8;
    const __half* gB0 = BscrH + (size_t)(nt * BN + ldR) * KTOT + ldC * 8;

    auto issue = [&](int kt) {
        const int s = kt % STAGES;
        const uint32_t sa = sbase + (uint32_t)s * STG_BYTES;
        const uint32_t sb = sa + TILE_H * 2;
        const uint32_t soff = (uint32_t)(ldR * ROWP + ldC * 8) * 2;
        const size_t kg = (size_t)kt * BK;
#pragma unroll
        for (int i = 0; i < 4; ++i) {
            cp16(sa + soff + i * 32 * ROWP * 2, gA0 + kg + (size_t)i * 32 * KTOT);
            cp16(sb + soff + i * 32 * ROWP * 2, gB0 + kg + (size_t)i * 32 * KTOT);
        }
        asm volatile("cp.async.commit_group;" ::: "memory");
    };

    // ldmatrix lane offset (bytes): rows (lane&15), k-half (lane>>4)*8 halves
    const uint32_t lmOff = (uint32_t)((lane & 15) * ROWP + (lane >> 4) * 8) * 2;
    const uint32_t aWarp = (uint32_t)(wm * 32 * ROWP) * 2 + lmOff;
    const uint32_t bWarp = (uint32_t)(wn * 64 * ROWP) * 2 + lmOff;

    auto compute = [&](int s) {
        const uint32_t sa = sbase + (uint32_t)s * STG_BYTES;
        const uint32_t sb = sa + TILE_H * 2;
#pragma unroll
        for (int ks = 0; ks < 4; ++ks) {
            const uint32_t kOff = ks * 32;  // 16 halves
            uint32_t a[2][4];
#pragma unroll
            for (int mt = 0; mt < 2; ++mt)
                ldsm_x4(a[mt][0], a[mt][1], a[mt][2], a[mt][3],
                        sa + aWarp + (uint32_t)(mt * 16 * ROWP) * 2 + kOff);
            // interleave: B-pair load -> 4 MMAs -> next B-pair ...
#pragma unroll
            for (int p = 0; p < 4; ++p) {
                uint32_t r0, r1, r2, r3;
                ldsm_x4(r0, r1, r2, r3,
                        sb + bWarp + (uint32_t)(p * 16 * ROWP) * 2 + kOff);
#pragma unroll
                for (int mt = 0; mt < 2; ++mt) {
                    mma_f16(acc[mt][2 * p],     a[mt], r0, r2, acc[mt][2 * p]);
                    mma_f16(acc[mt][2 * p + 1], a[mt], r1, r3, acc[mt][2 * p + 1]);
                }
            }
        }
    };

    issue(0);
    issue(1);

#pragma unroll 1
    for (int kt = 0; kt < KTILES; ++kt) {
        if (kt == KTILES - 1) {
            asm volatile("cp.async.wait_group 0;" ::: "memory");
        } else {
            asm volatile("cp.async.wait_group 1;" ::: "memory");
        }
        __syncthreads();
        if (kt + STAGES - 1 < KTILES) issue(kt + STAGES - 1);
        compute(kt % STAGES);
    }

    // ---------------- epilogue ----------------
    __syncthreads();
    float* zs = smem;
#pragma unroll
    for (int mt = 0; mt < 2; ++mt)
#pragma unroll
        for (int n = 0; n < 8; ++n)
#pragma unroll
            for (int c = 0; c < 4; ++c) {
                const int r = wm * 32 + mt * 16 + gid + ((c >= 2) ? 8 : 0);
                const int cc = wn * 64 + n * 8 + tig * 2 + (c & 1);
                zs[r * LDZ + cc] = acc[mt][n][c];
            }
    __syncthreads();

    float* outH = out + (size_t)BATCH * DH;
    const int jlane = tid & 31;
    const int hj0 = nt * 32 + jlane;
    const float bi = __ldg(bx + hj0)        + __ldg(bh + hj0);
    const float bf = __ldg(bx + 512 + hj0)  + __ldg(bh + 512 + hj0);
    const float bo = __ldg(bx + 1024 + hj0) + __ldg(bh + 1024 + hj0);
    const float bg = __ldg(bx + 1536 + hj0) + __ldg(bh + 1536 + hj0);
#pragma unroll 1
    for (int i = 0; i < 16; ++i) {
        const int idx = tid + i * THREADS;  // 0..4095
        const int m = idx >> 5;             // 0..127
        const float zi = zs[m * LDZ + jlane]      + bi;
        const float zf = zs[m * LDZ + 32 + jlane] + bf;
        const float zo = zs[m * LDZ + 64 + jlane] + bo;
        const float zg = zs[m * LDZ + 96 + jlane] + bg;
        const float ig = sigm(zi);
        const float fg = sigm(zf);
        const float og = sigm(zo);
        const float gg = tanh_fast(zg);
        const size_t goff = (size_t)(mBase + m) * DH + hj0;
        const float cnew = fg * Cin[goff] + ig * gg;
        out[goff] = cnew;
        outH[goff] = og * tanh_fast(cnew);
    }
}

extern "C" void kernel_launch(void* const* d_in, const int* in_sizes, int n_in,
                              void* d_out, int out_size) {
    const float* x = (const float*)d_in[0];
    const float* C = (const float*)d_in[1];
    const float* h = (const float*)d_in[2];
    const float* Wx = (const float*)d_in[3];
    const float* bx = (const float*)d_in[4];
    const float* Wh = (const float*)d_in[5];
    const float* bh = (const float*)d_in[6];
    float* out = (float*)d_out;

    cudaFuncSetAttribute(lstm_gemm, cudaFuncAttributeMaxDynamicSharedMemorySize,
                         SMEM_BYTES);

    prep_all<<<PREP_A_BLOCKS + PREP_B_BLOCKS, 256>>>(x, h, Wx, Wh);
    dim3 grid(NTOT / BN, BATCH / BM);  // (16, 256)
    lstm_gemm<<<grid, THREADS, SMEM_BYTES>>>(C, bx, bh, out);
}

// round 8
// speedup vs baseline: 1.7357x; 1.1407x over previous
#include <cuda_runtime.h>
#include <cuda_fp16.h>
#include <cstdint>

// Fused LSTM cell, sm_103 family-generic (no tcgen05 in this toolchain).
// Pass 1 (single kernel): fp32 -> fp16(rn):
//   AscrH = [x|h] (32768 x 1024 row-major)
//   BscrH = [Wx;Wh]^T gate-permuted [N'=2048][K=1024]:
//     n' = nt*128 + wn*64 + g*16 + jj  <->  weight col g*512 + nt*32 + wn*16 + jj
//   (warp-tile-local 16-wide gate blocks -> register-only LSTM epilogue)
// Pass 2: 128x128x1024 GEMM per CTA, 256 threads (8 warps, warp tile 32x64),
//   cp.async 3-stage pipeline, A-fragment double buffering, interleaved
//   ldmatrix.x4 + mma.sync.m16n8k16, register epilogue. 2 CTAs/SM.

#define BATCH 32768
#define DH 512
#define KTOT 1024
#define NTOT 2048

#define BM 128
#define BN 128
#define BK 64
#define KTILES (KTOT / BK)  // 16
#define STAGES 3
#define THREADS 256

#define ROWP 72                       // halves per smem row (64 + 8 pad)
#define TILE_H (128 * ROWP)           // 9216 halves per A/B tile
#define STG_BYTES (2 * TILE_H * 2)    // 36864 B
#define SMEM_BYTES (STAGES * STG_BYTES)  // 110592

#define PREP_A_BLOCKS 32768           // 8,388,608 float4 / 256
#define PREP_B_BLOCKS 2048            // 524,288 items / 256

// ---------------- device scratch ----------------
__device__ __half AscrH[(size_t)BATCH * KTOT];  // 64 MB
__device__ __half BscrH[(size_t)NTOT * KTOT];   // 4 MB

__device__ __forceinline__ uint32_t smem_u32(const void* p) {
    uint32_t a;
    asm("{ .reg .u64 t; cvta.to.shared.u64 t, %1; cvt.u32.u64 %0, t; }"
        : "=r"(a) : "l"(p));
    return a;
}
__device__ __forceinline__ void cp16(uint32_t sm, const void* g) {
    asm volatile("cp.async.cg.shared.global [%0], [%1], 16;"
                 :: "r"(sm), "l"(g) : "memory");
}
__device__ __forceinline__ void ldsm_x4(uint32_t& r0, uint32_t& r1,
                                        uint32_t& r2, uint32_t& r3,
                                        uint32_t addr) {
    asm volatile("ldmatrix.sync.aligned.m8n8.x4.shared.b16 {%0,%1,%2,%3}, [%4];"
                 : "=r"(r0), "=r"(r1), "=r"(r2), "=r"(r3) : "r"(addr));
}
__device__ __forceinline__ void mma_f16(float d[4], const uint32_t a[4],
                                        const uint32_t b0, const uint32_t b1,
                                        const float c[4]) {
    asm volatile(
        "mma.sync.aligned.m16n8k16.row.col.f32.f16.f16.f32 "
        "{%0,%1,%2,%3}, {%4,%5,%6,%7}, {%8,%9}, {%10,%11,%12,%13};\n"
        : "=f"(d[0]), "=f"(d[1]), "=f"(d[2]), "=f"(d[3])
        : "r"(a[0]), "r"(a[1]), "r"(a[2]), "r"(a[3]),
          "r"(b0), "r"(b1),
          "f"(c[0]), "f"(c[1]), "f"(c[2]), "f"(c[3]));
}

__device__ __forceinline__ float sigm(float v) { return 1.0f / (1.0f + __expf(-v)); }
__device__ __forceinline__ float tanh_fast(float v) {
    return 2.0f / (1.0f + __expf(-2.0f * v)) - 1.0f;
}

// ---------------- pass 1: merged conversion ----------------
__global__ void __launch_bounds__(256) prep_all(const float* __restrict__ x,
                                                const float* __restrict__ h,
                                                const float* __restrict__ Wx,
                                                const float* __restrict__ Wh) {
    if (blockIdx.x < PREP_A_BLOCKS) {
        size_t i = (size_t)blockIdx.x * 256 + threadIdx.x;  // float4 index
        size_t e = i * 4;
        int b = (int)(e >> 10);
        int k = (int)(e & 1023);
        const float* src = (k < 512) ? (x + (size_t)b * 512 + k)
                                     : (h + (size_t)b * 512 + (k - 512));
        float4 v = *(const float4*)src;
        __half2 h0 = __floats2half2_rn(v.x, v.y);
        __half2 h1 = __floats2half2_rn(v.z, v.w);
        uint2 o = make_uint2(*(uint32_t*)&h0, *(uint32_t*)&h1);
        *(uint2*)(AscrH + e) = o;
    } else {
        // BscrH[n'][k] = W[k][col]
        // n' = nt*128 + wn*64 + g*16 + jj, col = g*512 + nt*32 + wn*16 + jj
        size_t t = (size_t)(blockIdx.x - PREP_A_BLOCKS) * 256 + threadIdx.x;
        int np = (int)(t >> 8);          // n' 0..2047
        int kb = (int)(t & 255) * 4;     // k base
        int nt = np >> 7;
        int r = np & 127;
        int wn = r >> 6;
        int g = (r >> 4) & 3;
        int jj = r & 15;
        int col = g * 512 + nt * 32 + wn * 16 + jj;
        const float* src = (kb < 512) ? (Wx + (size_t)kb * NTOT + col)
                                      : (Wh + (size_t)(kb - 512) * NTOT + col);
        float v0 = src[0];
        float v1 = src[NTOT];
        float v2 = src[2 * NTOT];
        float v3 = src[3 * NTOT];
        __half2 h0 = __floats2half2_rn(v0, v1);
        __half2 h1 = __floats2half2_rn(v2, v3);
        uint2 o = make_uint2(*(uint32_t*)&h0, *(uint32_t*)&h1);
        *(uint2*)(BscrH + (size_t)np * KTOT + kb) = o;
    }
}

// ---------------- pass 2 ----------------
__global__ void __launch_bounds__(THREADS, 2)
lstm_gemm(const float* __restrict__ Cin, const float* __restrict__ bx,
          const float* __restrict__ bh, float* __restrict__ out) {
    extern __shared__ float smem[];
    const uint32_t sbase = smem_u32(smem);

    const int tid = threadIdx.x;
    const int warp = tid >> 5;
    const int lane = tid & 31;
    const int wm = warp & 3;   // 4 warps along M (32 rows each)
    const int wn = warp >> 2;  // 2 warps along N (64 cols each)
    const int gid = lane >> 2;
    const int tig = lane & 3;

    const int mBase = blockIdx.y * BM;
    const int nt = blockIdx.x;

    float acc[2][8][4];
#pragma unroll
    for (int mt = 0; mt < 2; ++mt)
#pragma unroll
        for (int n = 0; n < 8; ++n)
#pragma unroll
            for (int c = 0; c < 4; ++c) acc[mt][n][c] = 0.0f;

    // cp.async coordinates: 16B chunk = tid + i*256; row = chunk>>3, c = chunk&7
    const int ldR = tid >> 3;   // 0..31, +32 per i
    const int ldC = tid & 7;

    const __half* gA0 = AscrH + (size_t)(mBase + ldR) * KTOT + ldC * 8;
    const __half* gB0 = BscrH + (size_t)(nt * BN + ldR) * KTOT + ldC * 8;

    auto issue = [&](int kt) {
        const int s = kt % STAGES;
        const uint32_t sa = sbase + (uint32_t)s * STG_BYTES;
        const uint32_t sb = sa + TILE_H * 2;
        const uint32_t soff = (uint32_t)(ldR * ROWP + ldC * 8) * 2;
        const size_t kg = (size_t)kt * BK;
#pragma unroll
        for (int i = 0; i < 4; ++i) {
            cp16(sa + soff + i * 32 * ROWP * 2, gA0 + kg + (size_t)i * 32 * KTOT);
            cp16(sb + soff + i * 32 * ROWP * 2, gB0 + kg + (size_t)i * 32 * KTOT);
        }
        asm volatile("cp.async.commit_group;" ::: "memory");
    };

    // ldmatrix lane offset (bytes): rows (lane&15), k-half (lane>>4)*8 halves
    const uint32_t lmOff = (uint32_t)((lane & 15) * ROWP + (lane >> 4) * 8) * 2;
    const uint32_t aWarp = (uint32_t)(wm * 32 * ROWP) * 2 + lmOff;
    const uint32_t bWarp = (uint32_t)(wn * 64 * ROWP) * 2 + lmOff;

    auto compute = [&](int s) {
        const uint32_t sa = sbase + (uint32_t)s * STG_BYTES;
        const uint32_t sb = sa + TILE_H * 2;
        uint32_t abuf[2][2][4];
        // prefetch A fragments for ks=0
#pragma unroll
        for (int mt = 0; mt < 2; ++mt)
            ldsm_x4(abuf[0][mt][0], abuf[0][mt][1], abuf[0][mt][2], abuf[0][mt][3],
                    sa + aWarp + (uint32_t)(mt * 16 * ROWP) * 2);
#pragma unroll
        for (int ks = 0; ks < 4; ++ks) {
            const uint32_t kOff = ks * 32;  // 16 halves
            const int cur = ks & 1;
            if (ks < 3) {
#pragma unroll
                for (int mt = 0; mt < 2; ++mt)
                    ldsm_x4(abuf[cur ^ 1][mt][0], abuf[cur ^ 1][mt][1],
                            abuf[cur ^ 1][mt][2], abuf[cur ^ 1][mt][3],
                            sa + aWarp + (uint32_t)(mt * 16 * ROWP) * 2 + kOff + 32);
            }
            // interleave: B-pair load -> 4 MMAs -> next B-pair ...
#pragma unroll
            for (int p = 0; p < 4; ++p) {
                uint32_t r0, r1, r2, r3;
                ldsm_x4(r0, r1, r2, r3,
                        sb + bWarp + (uint32_t)(p * 16 * ROWP) * 2 + kOff);
#pragma unroll
                for (int mt = 0; mt < 2; ++mt) {
                    mma_f16(acc[mt][2 * p],     abuf[cur][mt], r0, r2, acc[mt][2 * p]);
                    mma_f16(acc[mt][2 * p + 1], abuf[cur][mt], r1, r3, acc[mt][2 * p + 1]);
                }
            }
        }
    };

    issue(0);
    issue(1);

#pragma unroll 1
    for (int kt = 0; kt < KTILES; ++kt) {
        if (kt == KTILES - 1) {
            asm volatile("cp.async.wait_group 0;" ::: "memory");
        } else {
            asm volatile("cp.async.wait_group 1;" ::: "memory");
        }
        __syncthreads();
        if (kt + STAGES - 1 < KTILES) issue(kt + STAGES - 1);
        compute(kt % STAGES);
    }

    // ---------------- register epilogue ----------------
    // acc[mt][n][c]: gate = n>>1, jhalf = n&1;
    //   row = mBase + wm*32 + mt*16 + gid + (c>=2)*8
    //   jj  = jhalf*8 + tig*2 + (c&1);  hidden j = nt*32 + wn*16 + jj
    const int hjBase = nt * 32 + wn * 16;
    float biasI[4], biasF[4], biasO[4], biasG[4];
#pragma unroll
    for (int jh = 0; jh < 2; ++jh)
#pragma unroll
        for (int c1 = 0; c1 < 2; ++c1) {
            const int hj = hjBase + jh * 8 + tig * 2 + c1;
            biasI[jh * 2 + c1] = __ldg(bx + hj)        + __ldg(bh + hj);
            biasF[jh * 2 + c1] = __ldg(bx + 512 + hj)  + __ldg(bh + 512 + hj);
            biasO[jh * 2 + c1] = __ldg(bx + 1024 + hj) + __ldg(bh + 1024 + hj);
            biasG[jh * 2 + c1] = __ldg(bx + 1536 + hj) + __ldg(bh + 1536 + hj);
        }

    float* outH = out + (size_t)BATCH * DH;
#pragma unroll
    for (int mt = 0; mt < 2; ++mt)
#pragma unroll
        for (int rh = 0; rh < 2; ++rh)
#pragma unroll
            for (int jh = 0; jh < 2; ++jh) {
                const int row = mBase + wm * 32 + mt * 16 + gid + rh * 8;
                const int jj0 = jh * 8 + tig * 2;
                const size_t goff = (size_t)row * DH + hjBase + jj0;
                const float2 cin = *(const float2*)(Cin + goff);
                float2 cnew, hnew;
#pragma unroll
                for (int c1 = 0; c1 < 2; ++c1) {
                    const int c = rh * 2 + c1;
                    const int bidx = jh * 2 + c1;
                    const float zi = acc[mt][jh][c]     + biasI[bidx];
                    const float zf = acc[mt][2 + jh][c] + biasF[bidx];
                    const float zo = acc[mt][4 + jh][c] + biasO[bidx];
                    const float zg = acc[mt][6 + jh][c] + biasG[bidx];
                    const float ig = sigm(zi);
                    const float fg = sigm(zf);
                    const float og = sigm(zo);
                    const float gg = tanh_fast(zg);
                    const float cv = fg * ((c1 == 0) ? cin.x : cin.y) + ig * gg;
                    const float hv = og * tanh_fast(cv);
                    if (c1 == 0) { cnew.x = cv; hnew.x = hv; }
                    else         { cnew.y = cv; hnew.y = hv; }
                }
                *(float2*)(out + goff) = cnew;
                *(float2*)(outH + goff) = hnew;
            }
}

extern "C" void kernel_launch(void* const* d_in, const int* in_sizes, int n_in,
                              void* d_out, int out_size) {
    const float* x = (const float*)d_in[0];
    const float* C = (const float*)d_in[1];
    const float* h = (const float*)d_in[2];
    const float* Wx = (const float*)d_in[3];
    const float* bx = (const float*)d_in[4];
    const float* Wh = (const float*)d_in[5];
    const float* bh = (const float*)d_in[6];
    float* out = (float*)d_out;

    cudaFuncSetAttribute(lstm_gemm, cudaFuncAttributeMaxDynamicSharedMemorySize,
                         SMEM_BYTES);

    prep_all<<<PREP_A_BLOCKS + PREP_B_BLOCKS, 256>>>(x, h, Wx, Wh);
    dim3 grid(NTOT / BN, BATCH / BM);  // (16, 256)
    lstm_gemm<<<grid, THREADS, SMEM_BYTES>>>(C, bx, bh, out);
}

// round 9
// speedup vs baseline: 1.9464x; 1.1214x over previous
#include <cuda_runtime.h>
#include <cuda_fp16.h>
#include <cstdint>

// Fused LSTM cell, sm_103 family-generic (no tcgen05 in this toolchain).
// Pass 1 (single kernel): fp32 -> fp16(rn):
//   AscrH = [x|h] (32768 x 1024 row-major)
//   BscrH = [Wx;Wh]^T gate-permuted [N'=2048][K=1024]:
//     n' = nt*128 + wn*64 + g*16 + jj  <->  weight col g*512 + nt*32 + wn*16 + jj
// Pass 2: 128x128x1024 GEMM per CTA, 256 threads (8 warps, warp tile 32x64),
//   cp.async 3-stage pipeline (fully unrolled K loop, compile-time stages),
//   A- and B-fragment double buffering, mma.sync.m16n8k16, register LSTM
//   epilogue. 2 CTAs/SM (16 warps/SM).

#define BATCH 32768
#define DH 512
#define KTOT 1024
#define NTOT 2048

#define BM 128
#define BN 128
#define BK 64
#define KTILES (KTOT / BK)  // 16
#define STAGES 3
#define THREADS 256

#define ROWP 72                       // halves per smem row (64 + 8 pad)
#define TILE_H (128 * ROWP)           // 9216 halves per A/B tile
#define STG_BYTES (2 * TILE_H * 2)    // 36864 B
#define SMEM_BYTES (STAGES * STG_BYTES)  // 110592

#define PREP_A_BLOCKS 32768           // 8,388,608 float4 / 256
#define PREP_B_BLOCKS 2048            // 524,288 items / 256

// ---------------- device scratch ----------------
__device__ __half AscrH[(size_t)BATCH * KTOT];  // 64 MB
__device__ __half BscrH[(size_t)NTOT * KTOT];   // 4 MB

__device__ __forceinline__ uint32_t smem_u32(const void* p) {
    uint32_t a;
    asm("{ .reg .u64 t; cvta.to.shared.u64 t, %1; cvt.u32.u64 %0, t; }"
        : "=r"(a) : "l"(p));
    return a;
}
__device__ __forceinline__ void cp16(uint32_t sm, const void* g) {
    asm volatile("cp.async.cg.shared.global [%0], [%1], 16;"
                 :: "r"(sm), "l"(g) : "memory");
}
__device__ __forceinline__ void ldsm_x4(uint32_t& r0, uint32_t& r1,
                                        uint32_t& r2, uint32_t& r3,
                                        uint32_t addr) {
    asm volatile("ldmatrix.sync.aligned.m8n8.x4.shared.b16 {%0,%1,%2,%3}, [%4];"
                 : "=r"(r0), "=r"(r1), "=r"(r2), "=r"(r3) : "r"(addr));
}
__device__ __forceinline__ void mma_f16(float d[4], const uint32_t a[4],
                                        const uint32_t b0, const uint32_t b1,
                                        const float c[4]) {
    asm volatile(
        "mma.sync.aligned.m16n8k16.row.col.f32.f16.f16.f32 "
        "{%0,%1,%2,%3}, {%4,%5,%6,%7}, {%8,%9}, {%10,%11,%12,%13};\n"
        : "=f"(d[0]), "=f"(d[1]), "=f"(d[2]), "=f"(d[3])
        : "r"(a[0]), "r"(a[1]), "r"(a[2]), "r"(a[3]),
          "r"(b0), "r"(b1),
          "f"(c[0]), "f"(c[1]), "f"(c[2]), "f"(c[3]));
}

__device__ __forceinline__ float sigm(float v) { return 1.0f / (1.0f + __expf(-v)); }
__device__ __forceinline__ float tanh_fast(float v) {
    return 2.0f / (1.0f + __expf(-2.0f * v)) - 1.0f;
}

// ---------------- pass 1: merged conversion ----------------
__global__ void __launch_bounds__(256) prep_all(const float* __restrict__ x,
                                                const float* __restrict__ h,
                                                const float* __restrict__ Wx,
                                                const float* __restrict__ Wh) {
    if (blockIdx.x < PREP_A_BLOCKS) {
        size_t i = (size_t)blockIdx.x * 256 + threadIdx.x;  // float4 index
        size_t e = i * 4;
        int b = (int)(e >> 10);
        int k = (int)(e & 1023);
        const float* src = (k < 512) ? (x + (size_t)b * 512 + k)
                                     : (h + (size_t)b * 512 + (k - 512));
        float4 v = *(const float4*)src;
        __half2 h0 = __floats2half2_rn(v.x, v.y);
        __half2 h1 = __floats2half2_rn(v.z, v.w);
        uint2 o = make_uint2(*(uint32_t*)&h0, *(uint32_t*)&h1);
        *(uint2*)(AscrH + e) = o;
    } else {
        // BscrH[n'][k] = W[k][col]
        // n' = nt*128 + wn*64 + g*16 + jj, col = g*512 + nt*32 + wn*16 + jj
        size_t t = (size_t)(blockIdx.x - PREP_A_BLOCKS) * 256 + threadIdx.x;
        int np = (int)(t >> 8);          // n' 0..2047
        int kb = (int)(t & 255) * 4;     // k base
        int nt = np >> 7;
        int r = np & 127;
        int wn = r >> 6;
        int g = (r >> 4) & 3;
        int jj = r & 15;
        int col = g * 512 + nt * 32 + wn * 16 + jj;
        const float* src = (kb < 512) ? (Wx + (size_t)kb * NTOT + col)
                                      : (Wh + (size_t)(kb - 512) * NTOT + col);
        float v0 = src[0];
        float v1 = src[NTOT];
        float v2 = src[2 * NTOT];
        float v3 = src[3 * NTOT];
        __half2 h0 = __floats2half2_rn(v0, v1);
        __half2 h1 = __floats2half2_rn(v2, v3);
        uint2 o = make_uint2(*(uint32_t*)&h0, *(uint32_t*)&h1);
        *(uint2*)(BscrH + (size_t)np * KTOT + kb) = o;
    }
}

// ---------------- pass 2 ----------------
__global__ void __launch_bounds__(THREADS, 2)
lstm_gemm(const float* __restrict__ Cin, const float* __restrict__ bx,
          const float* __restrict__ bh, float* __restrict__ out) {
    extern __shared__ float smem[];
    const uint32_t sbase = smem_u32(smem);

    const int tid = threadIdx.x;
    const int warp = tid >> 5;
    const int lane = tid & 31;
    const int wm = warp & 3;   // 4 warps along M (32 rows each)
    const int wn = warp >> 2;  // 2 warps along N (64 cols each)
    const int gid = lane >> 2;
    const int tig = lane & 3;

    const int mBase = blockIdx.y * BM;
    const int nt = blockIdx.x;

    float acc[2][8][4];
#pragma unroll
    for (int mt = 0; mt < 2; ++mt)
#pragma unroll
        for (int n = 0; n < 8; ++n)
#pragma unroll
            for (int c = 0; c < 4; ++c) acc[mt][n][c] = 0.0f;

    // cp.async coordinates: 16B chunk = tid + i*256; row = chunk>>3, c = chunk&7
    const int ldR = tid >> 3;   // 0..31, +32 per i
    const int ldC = tid & 7;

    const __half* gA0 = AscrH + (size_t)(mBase + ldR) * KTOT + ldC * 8;
    const __half* gB0 = BscrH + (size_t)(nt * BN + ldR) * KTOT + ldC * 8;
    const uint32_t soff = (uint32_t)(ldR * ROWP + ldC * 8) * 2;

    // ldmatrix lane offset (bytes): rows (lane&15), k-half (lane>>4)*8 halves
    const uint32_t lmOff = (uint32_t)((lane & 15) * ROWP + (lane >> 4) * 8) * 2;
    const uint32_t aWarp = (uint32_t)(wm * 32 * ROWP) * 2 + lmOff;
    const uint32_t bWarp = (uint32_t)(wn * 64 * ROWP) * 2 + lmOff;

    auto issue = [&](int kt) {
        const int s = kt % STAGES;                     // compile-time under unroll
        const uint32_t sa = sbase + (uint32_t)s * STG_BYTES;
        const uint32_t sb = sa + TILE_H * 2;
        const size_t kg = (size_t)kt * BK;
#pragma unroll
        for (int i = 0; i < 4; ++i) {
            cp16(sa + soff + i * 32 * ROWP * 2, gA0 + kg + (size_t)i * 32 * KTOT);
            cp16(sb + soff + i * 32 * ROWP * 2, gB0 + kg + (size_t)i * 32 * KTOT);
        }
        asm volatile("cp.async.commit_group;" ::: "memory");
    };

    auto compute = [&](int s) {                        // s compile-time under unroll
        const uint32_t sa = sbase + (uint32_t)s * STG_BYTES + aWarp;
        const uint32_t sb = sbase + (uint32_t)s * STG_BYTES + TILE_H * 2 + bWarp;
        uint32_t abuf[2][2][4];
        uint32_t bbuf[2][4];
        // prefetch A (ks=0) and B (p=0)
#pragma unroll
        for (int mt = 0; mt < 2; ++mt)
            ldsm_x4(abuf[0][mt][0], abuf[0][mt][1], abuf[0][mt][2], abuf[0][mt][3],
                    sa + (uint32_t)(mt * 16 * ROWP) * 2);
        ldsm_x4(bbuf[0][0], bbuf[0][1], bbuf[0][2], bbuf[0][3], sb);
#pragma unroll
        for (int ks = 0; ks < 4; ++ks) {
            const uint32_t kOff = ks * 32;  // 16 halves
            const int cur = ks & 1;
            if (ks < 3) {
#pragma unroll
                for (int mt = 0; mt < 2; ++mt)
                    ldsm_x4(abuf[cur ^ 1][mt][0], abuf[cur ^ 1][mt][1],
                            abuf[cur ^ 1][mt][2], abuf[cur ^ 1][mt][3],
                            sa + (uint32_t)(mt * 16 * ROWP) * 2 + kOff + 32);
            }
#pragma unroll
            for (int p = 0; p < 4; ++p) {
                const int bc = p & 1;
                if (p < 3) {
                    ldsm_x4(bbuf[bc ^ 1][0], bbuf[bc ^ 1][1],
                            bbuf[bc ^ 1][2], bbuf[bc ^ 1][3],
                            sb + (uint32_t)((p + 1) * 16 * ROWP) * 2 + kOff);
                } else if (ks < 3) {
                    ldsm_x4(bbuf[bc ^ 1][0], bbuf[bc ^ 1][1],
                            bbuf[bc ^ 1][2], bbuf[bc ^ 1][3],
                            sb + kOff + 32);
                }
#pragma unroll
                for (int mt = 0; mt < 2; ++mt) {
                    mma_f16(acc[mt][2 * p],     abuf[cur][mt], bbuf[bc][0],
                            bbuf[bc][2], acc[mt][2 * p]);
                    mma_f16(acc[mt][2 * p + 1], abuf[cur][mt], bbuf[bc][1],
                            bbuf[bc][3], acc[mt][2 * p + 1]);
                }
            }
            // bbuf[(3&1)^1] = bbuf[0] now holds B(p=0) of next ks (loaded above)
        }
    };

    issue(0);
    issue(1);

#pragma unroll
    for (int kt = 0; kt < KTILES; ++kt) {
        if (kt == KTILES - 1) {
            asm volatile("cp.async.wait_group 0;" ::: "memory");
        } else {
            asm volatile("cp.async.wait_group 1;" ::: "memory");
        }
        __syncthreads();
        if (kt + STAGES - 1 < KTILES) issue(kt + STAGES - 1);
        compute(kt % STAGES);
    }

    // ---------------- register epilogue ----------------
    // acc[mt][n][c]: gate = n>>1, jhalf = n&1;
    //   row = mBase + wm*32 + mt*16 + gid + (c>=2)*8
    //   jj  = jhalf*8 + tig*2 + (c&1);  hidden j = nt*32 + wn*16 + jj
    const int hjBase = nt * 32 + wn * 16;
    float biasI[4], biasF[4], biasO[4], biasG[4];
#pragma unroll
    for (int jh = 0; jh < 2; ++jh)
#pragma unroll
        for (int c1 = 0; c1 < 2; ++c1) {
            const int hj = hjBase + jh * 8 + tig * 2 + c1;
            biasI[jh * 2 + c1] = __ldg(bx + hj)        + __ldg(bh + hj);
            biasF[jh * 2 + c1] = __ldg(bx + 512 + hj)  + __ldg(bh + 512 + hj);
            biasO[jh * 2 + c1] = __ldg(bx + 1024 + hj) + __ldg(bh + 1024 + hj);
            biasG[jh * 2 + c1] = __ldg(bx + 1536 + hj) + __ldg(bh + 1536 + hj);
        }

    float* outH = out + (size_t)BATCH * DH;
#pragma unroll
    for (int mt = 0; mt < 2; ++mt)
#pragma unroll
        for (int rh = 0; rh < 2; ++rh)
#pragma unroll
            for (int jh = 0; jh < 2; ++jh) {
                const int row = mBase + wm * 32 + mt * 16 + gid + rh * 8;
                const int jj0 = jh * 8 + tig * 2;
                const size_t goff = (size_t)row * DH + hjBase + jj0;
                const float2 cin = *(const float2*)(Cin + goff);
                float2 cnew, hnew;
#pragma unroll
                for (int c1 = 0; c1 < 2; ++c1) {
                    const int c = rh * 2 + c1;
                    const int bidx = jh * 2 + c1;
                    const float zi = acc[mt][jh][c]     + biasI[bidx];
                    const float zf = acc[mt][2 + jh][c] + biasF[bidx];
                    const float zo = acc[mt][4 + jh][c] + biasO[bidx];
                    const float zg = acc[mt][6 + jh][c] + biasG[bidx];
                    const float ig = sigm(zi);
                    const float fg = sigm(zf);
                    const float og = sigm(zo);
                    const float gg = tanh_fast(zg);
                    const float cv = fg * ((c1 == 0) ? cin.x : cin.y) + ig * gg;
                    const float hv = og * tanh_fast(cv);
                    if (c1 == 0) { cnew.x = cv; hnew.x = hv; }
                    else         { cnew.y = cv; hnew.y = hv; }
                }
                *(float2*)(out + goff) = cnew;
                *(float2*)(outH + goff) = hnew;
            }
}

extern "C" void kernel_launch(void* const* d_in, const int* in_sizes, int n_in,
                              void* d_out, int out_size) {
    const float* x = (const float*)d_in[0];
    const float* C = (const float*)d_in[1];
    const float* h = (const float*)d_in[2];
    const float* Wx = (const float*)d_in[3];
    const float* bx = (const float*)d_in[4];
    const float* Wh = (const float*)d_in[5];
    const float* bh = (const float*)d_in[6];
    float* out = (float*)d_out;

    cudaFuncSetAttribute(lstm_gemm, cudaFuncAttributeMaxDynamicSharedMemorySize,
                         SMEM_BYTES);

    prep_all<<<PREP_A_BLOCKS + PREP_B_BLOCKS, 256>>>(x, h, Wx, Wh);
    dim3 grid(NTOT / BN, BATCH / BM);  // (16, 256)
    lstm_gemm<<<grid, THREADS, SMEM_BYTES>>>(C, bx, bh, out);
}

// round 10
// speedup vs baseline: 2.1536x; 1.1064x over previous
#include <cuda_runtime.h>
#include <cuda_fp16.h>
#include <cstdint>

// Fused LSTM cell, sm_103 family-generic (no tcgen05 in this toolchain).
// Pass 1 (single kernel): fp32 -> fp16(rn):
//   AscrH = [x|h] (32768 x 1024 row-major)
//   BscrH = [Wx;Wh]^T gate-permuted [N'=2048][K=1024]:
//     n' = nt*128 + wn*64 + g*16 + jj  <->  weight col g*512 + nt*32 + wn*16 + jj
// Pass 2: 128x128x1024 GEMM per CTA, 256 threads (8 warps, warp tile 32x64),
//   cp.async 3-stage pipeline with PER-STAGE MBARRIERS (no __syncthreads in
//   the main loop), A/B fragment double buffering, mma.sync.m16n8k16,
//   register LSTM epilogue. 2 CTAs/SM (16 warps/SM).

#define BATCH 32768
#define DH 512
#define KTOT 1024
#define NTOT 2048

#define BM 128
#define BN 128
#define BK 64
#define KTILES (KTOT / BK)  // 16
#define STAGES 3
#define THREADS 256

#define ROWP 72                       // halves per smem row (64 + 8 pad)
#define TILE_H (128 * ROWP)           // 9216 halves per A/B tile
#define STG_BYTES (2 * TILE_H * 2)    // 36864 B
#define STAGE_OFF 1024
#define SMEM_BYTES (STAGE_OFF + STAGES * STG_BYTES)  // 111616

#define PREP_A_BLOCKS 32768           // 8,388,608 float4 / 256
#define PREP_B_BLOCKS 2048            // 524,288 items / 256

// ---------------- device scratch ----------------
__device__ __half AscrH[(size_t)BATCH * KTOT];  // 64 MB
__device__ __half BscrH[(size_t)NTOT * KTOT];   // 4 MB

__device__ __forceinline__ uint32_t smem_u32(const void* p) {
    uint32_t a;
    asm("{ .reg .u64 t; cvta.to.shared.u64 t, %1; cvt.u32.u64 %0, t; }"
        : "=r"(a) : "l"(p));
    return a;
}
__device__ __forceinline__ void cp16(uint32_t sm, const void* g) {
    asm volatile("cp.async.cg.shared.global [%0], [%1], 16;"
                 :: "r"(sm), "l"(g) : "memory");
}
#define MBARRIER_INIT(addr, cnt) \
    asm volatile("mbarrier.init.shared.b64 [%0], %1;" :: "r"(addr), "r"(cnt) : "memory")
#define MBARRIER_ARRIVE(addr) \
    asm volatile("mbarrier.arrive.shared.b64 _, [%0];" :: "r"(addr) : "memory")
#define CP_ASYNC_MBAR_ARRIVE(addr) \
    asm volatile("cp.async.mbarrier.arrive.noinc.shared.b64 [%0];" \
                 :: "r"(addr) : "memory")
#define MBARRIER_WAIT_PARITY(addr, par) do {                                   \
    uint32_t _m = (addr), _p = (par), _d;                                      \
    asm volatile("{\n\t.reg .pred p;\n\t"                                      \
        "mbarrier.try_wait.parity.acquire.cta.shared::cta.b64 p, [%1], %2;\n\t"\
        "selp.b32 %0, 1, 0, p;\n\t}"                                           \
        : "=r"(_d) : "r"(_m), "r"(_p) : "memory");                             \
    if (!_d) {                                                                 \
        asm volatile("{\n\t.reg .pred P1;\n\t"                                 \
            "WL_%=:\n\t"                                                       \
            "mbarrier.try_wait.parity.acquire.cta.shared::cta.b64 P1, [%0], %1, 0x989680;\n\t" \
            "@P1 bra.uni WD_%=;\n\t"                                           \
            "bra.uni WL_%=;\n\t"                                               \
            "WD_%=:\n\t}" :: "r"(_m), "r"(_p) : "memory");                     \
    }                                                                          \
} while (0)

__device__ __forceinline__ void ldsm_x4(uint32_t& r0, uint32_t& r1,
                                        uint32_t& r2, uint32_t& r3,
                                        uint32_t addr) {
    asm volatile("ldmatrix.sync.aligned.m8n8.x4.shared.b16 {%0,%1,%2,%3}, [%4];"
                 : "=r"(r0), "=r"(r1), "=r"(r2), "=r"(r3) : "r"(addr));
}
__device__ __forceinline__ void mma_f16(float d[4], const uint32_t a[4],
                                        const uint32_t b0, const uint32_t b1,
                                        const float c[4]) {
    asm volatile(
        "mma.sync.aligned.m16n8k16.row.col.f32.f16.f16.f32 "
        "{%0,%1,%2,%3}, {%4,%5,%6,%7}, {%8,%9}, {%10,%11,%12,%13};\n"
        : "=f"(d[0]), "=f"(d[1]), "=f"(d[2]), "=f"(d[3])
        : "r"(a[0]), "r"(a[1]), "r"(a[2]), "r"(a[3]),
          "r"(b0), "r"(b1),
          "f"(c[0]), "f"(c[1]), "f"(c[2]), "f"(c[3]));
}

__device__ __forceinline__ float sigm(float v) { return 1.0f / (1.0f + __expf(-v)); }
__device__ __forceinline__ float tanh_fast(float v) {
    return 2.0f / (1.0f + __expf(-2.0f * v)) - 1.0f;
}

// ---------------- pass 1: merged conversion ----------------
__global__ void __launch_bounds__(256) prep_all(const float* __restrict__ x,
                                                const float* __restrict__ h,
                                                const float* __restrict__ Wx,
                                                const float* __restrict__ Wh) {
    if (blockIdx.x < PREP_A_BLOCKS) {
        size_t i = (size_t)blockIdx.x * 256 + threadIdx.x;  // float4 index
        size_t e = i * 4;
        int b = (int)(e >> 10);
        int k = (int)(e & 1023);
        const float* src = (k < 512) ? (x + (size_t)b * 512 + k)
                                     : (h + (size_t)b * 512 + (k - 512));
        float4 v = *(const float4*)src;
        __half2 h0 = __floats2half2_rn(v.x, v.y);
        __half2 h1 = __floats2half2_rn(v.z, v.w);
        uint2 o = make_uint2(*(uint32_t*)&h0, *(uint32_t*)&h1);
        *(uint2*)(AscrH + e) = o;
    } else {
        // BscrH[n'][k] = W[k][col]
        // n' = nt*128 + wn*64 + g*16 + jj, col = g*512 + nt*32 + wn*16 + jj
        size_t t = (size_t)(blockIdx.x - PREP_A_BLOCKS) * 256 + threadIdx.x;
        int np = (int)(t >> 8);          // n' 0..2047
        int kb = (int)(t & 255) * 4;     // k base
        int nt = np >> 7;
        int r = np & 127;
        int wn = r >> 6;
        int g = (r >> 4) & 3;
        int jj = r & 15;
        int col = g * 512 + nt * 32 + wn * 16 + jj;
        const float* src = (kb < 512) ? (Wx + (size_t)kb * NTOT + col)
                                      : (Wh + (size_t)(kb - 512) * NTOT + col);
        float v0 = src[0];
        float v1 = src[NTOT];
        float v2 = src[2 * NTOT];
        float v3 = src[3 * NTOT];
        __half2 h0 = __floats2half2_rn(v0, v1);
        __half2 h1 = __floats2half2_rn(v2, v3);
        uint2 o = make_uint2(*(uint32_t*)&h0, *(uint32_t*)&h1);
        *(uint2*)(BscrH + (size_t)np * KTOT + kb) = o;
    }
}

// ---------------- pass 2 ----------------
__global__ void __launch_bounds__(THREADS, 2)
lstm_gemm(const float* __restrict__ Cin, const float* __restrict__ bx,
          const float* __restrict__ bh, float* __restrict__ out) {
    extern __shared__ float smem[];
    const uint32_t sbase = smem_u32(smem);

    const int tid = threadIdx.x;
    const int warp = tid >> 5;
    const int lane = tid & 31;
    const int wm = warp & 3;   // 4 warps along M (32 rows each)
    const int wn = warp >> 2;  // 2 warps along N (64 cols each)
    const int gid = lane >> 2;
    const int tig = lane & 3;

    const int mBase = blockIdx.y * BM;
    const int nt = blockIdx.x;

    // mbarriers: full[s] = sbase + s*16, empty[s] = sbase + s*16 + 8
    if (tid == 0) {
#pragma unroll
        for (int s = 0; s < STAGES; ++s) {
            MBARRIER_INIT(sbase + s * 16, THREADS);  // full: cp.async arrivals
            MBARRIER_INIT(sbase + s * 16 + 8, 8);    // empty: 1 per warp
        }
    }
    __syncthreads();

    float acc[2][8][4];
#pragma unroll
    for (int mt = 0; mt < 2; ++mt)
#pragma unroll
        for (int n = 0; n < 8; ++n)
#pragma unroll
            for (int c = 0; c < 4; ++c) acc[mt][n][c] = 0.0f;

    // cp.async coordinates: 16B chunk = tid + i*256; row = chunk>>3, c = chunk&7
    const int ldR = tid >> 3;   // 0..31, +32 per i
    const int ldC = tid & 7;

    const __half* gA0 = AscrH + (size_t)(mBase + ldR) * KTOT + ldC * 8;
    const __half* gB0 = BscrH + (size_t)(nt * BN + ldR) * KTOT + ldC * 8;
    const uint32_t soff = (uint32_t)(ldR * ROWP + ldC * 8) * 2;

    // ldmatrix lane offset (bytes): rows (lane&15), k-half (lane>>4)*8 halves
    const uint32_t lmOff = (uint32_t)((lane & 15) * ROWP + (lane >> 4) * 8) * 2;
    const uint32_t aWarp = (uint32_t)(wm * 32 * ROWP) * 2 + lmOff;
    const uint32_t bWarp = (uint32_t)(wn * 64 * ROWP) * 2 + lmOff;

    auto issue = [&](int kt) {                         // kt compile-time
        const int s = kt % STAGES;
        MBARRIER_WAIT_PARITY(sbase + s * 16 + 8, ((kt / 3) & 1) ^ 1);
        const uint32_t sa = sbase + STAGE_OFF + (uint32_t)s * STG_BYTES;
        const uint32_t sb = sa + TILE_H * 2;
        const size_t kg = (size_t)kt * BK;
#pragma unroll
        for (int i = 0; i < 4; ++i) {
            cp16(sa + soff + i * 32 * ROWP * 2, gA0 + kg + (size_t)i * 32 * KTOT);
            cp16(sb + soff + i * 32 * ROWP * 2, gB0 + kg + (size_t)i * 32 * KTOT);
        }
        CP_ASYNC_MBAR_ARRIVE(sbase + s * 16);
    };

    auto compute = [&](int kt) {                       // kt compile-time
        const int s = kt % STAGES;
        MBARRIER_WAIT_PARITY(sbase + s * 16, (kt / 3) & 1);
        const uint32_t sa = sbase + STAGE_OFF + (uint32_t)s * STG_BYTES + aWarp;
        const uint32_t sb = sbase + STAGE_OFF + (uint32_t)s * STG_BYTES + TILE_H * 2 + bWarp;
        uint32_t abuf[2][2][4];
        uint32_t bbuf[2][4];
#pragma unroll
        for (int mt = 0; mt < 2; ++mt)
            ldsm_x4(abuf[0][mt][0], abuf[0][mt][1], abuf[0][mt][2], abuf[0][mt][3],
                    sa + (uint32_t)(mt * 16 * ROWP) * 2);
        ldsm_x4(bbuf[0][0], bbuf[0][1], bbuf[0][2], bbuf[0][3], sb);
#pragma unroll
        for (int ks = 0; ks < 4; ++ks) {
            const uint32_t kOff = ks * 32;  // 16 halves
            const int cur = ks & 1;
            if (ks < 3) {
#pragma unroll
                for (int mt = 0; mt < 2; ++mt)
                    ldsm_x4(abuf[cur ^ 1][mt][0], abuf[cur ^ 1][mt][1],
                            abuf[cur ^ 1][mt][2], abuf[cur ^ 1][mt][3],
                            sa + (uint32_t)(mt * 16 * ROWP) * 2 + kOff + 32);
            }
#pragma unroll
            for (int p = 0; p < 4; ++p) {
                const int bc = p & 1;
                if (p < 3) {
                    ldsm_x4(bbuf[bc ^ 1][0], bbuf[bc ^ 1][1],
                            bbuf[bc ^ 1][2], bbuf[bc ^ 1][3],
                            sb + (uint32_t)((p + 1) * 16 * ROWP) * 2 + kOff);
                } else if (ks < 3) {
                    ldsm_x4(bbuf[bc ^ 1][0], bbuf[bc ^ 1][1],
                            bbuf[bc ^ 1][2], bbuf[bc ^ 1][3],
                            sb + kOff + 32);
                }
#pragma unroll
                for (int mt = 0; mt < 2; ++mt) {
                    mma_f16(acc[mt][2 * p],     abuf[cur][mt], bbuf[bc][0],
                            bbuf[bc][2], acc[mt][2 * p]);
                    mma_f16(acc[mt][2 * p + 1], abuf[cur][mt], bbuf[bc][1],
                            bbuf[bc][3], acc[mt][2 * p + 1]);
                }
            }
        }
        __syncwarp();
        if (lane == 0) MBARRIER_ARRIVE(sbase + s * 16 + 8);
    };

    issue(0);
    issue(1);

#pragma unroll
    for (int kt = 0; kt < KTILES; ++kt) {
        compute(kt);
        if (kt + 2 < KTILES) issue(kt + 2);
    }

    // ---------------- register epilogue ----------------
    // acc[mt][n][c]: gate = n>>1, jhalf = n&1;
    //   row = mBase + wm*32 + mt*16 + gid + (c>=2)*8
    //   jj  = jhalf*8 + tig*2 + (c&1);  hidden j = nt*32 + wn*16 + jj
    const int hjBase = nt * 32 + wn * 16;
    float biasI[4], biasF[4], biasO[4], biasG[4];
#pragma unroll
    for (int jh = 0; jh < 2; ++jh)
#pragma unroll
        for (int c1 = 0; c1 < 2; ++c1) {
            const int hj = hjBase + jh * 8 + tig * 2 + c1;
            biasI[jh * 2 + c1] = __ldg(bx + hj)        + __ldg(bh + hj);
            biasF[jh * 2 + c1] = __ldg(bx + 512 + hj)  + __ldg(bh + 512 + hj);
            biasO[jh * 2 + c1] = __ldg(bx + 1024 + hj) + __ldg(bh + 1024 + hj);
            biasG[jh * 2 + c1] = __ldg(bx + 1536 + hj) + __ldg(bh + 1536 + hj);
        }

    float* outH = out + (size_t)BATCH * DH;
#pragma unroll
    for (int mt = 0; mt < 2; ++mt)
#pragma unroll
        for (int rh = 0; rh < 2; ++rh)
#pragma unroll
            for (int jh = 0; jh < 2; ++jh) {
                const int row = mBase + wm * 32 + mt * 16 + gid + rh * 8;
                const int jj0 = jh * 8 + tig * 2;
                const size_t goff = (size_t)row * DH + hjBase + jj0;
                const float2 cin = *(const float2*)(Cin + goff);
                float2 cnew, hnew;
#pragma unroll
                for (int c1 = 0; c1 < 2; ++c1) {
                    const int c = rh * 2 + c1;
                    const int bidx = jh * 2 + c1;
                    const float zi = acc[mt][jh][c]     + biasI[bidx];
                    const float zf = acc[mt][2 + jh][c] + biasF[bidx];
                    const float zo = acc[mt][4 + jh][c] + biasO[bidx];
                    const float zg = acc[mt][6 + jh][c] + biasG[bidx];
                    const float ig = sigm(zi);
                    const float fg = sigm(zf);
                    const float og = sigm(zo);
                    const float gg = tanh_fast(zg);
                    const float cv = fg * ((c1 == 0) ? cin.x : cin.y) + ig * gg;
                    const float hv = og * tanh_fast(cv);
                    if (c1 == 0) { cnew.x = cv; hnew.x = hv; }
                    else         { cnew.y = cv; hnew.y = hv; }
                }
                *(float2*)(out + goff) = cnew;
                *(float2*)(outH + goff) = hnew;
            }
}

extern "C" void kernel_launch(void* const* d_in, const int* in_sizes, int n_in,
                              void* d_out, int out_size) {
    const float* x = (const float*)d_in[0];
    const float* C = (const float*)d_in[1];
    const float* h = (const float*)d_in[2];
    const float* Wx = (const float*)d_in[3];
    const float* bx = (const float*)d_in[4];
    const float* Wh = (const float*)d_in[5];
    const float* bh = (const float*)d_in[6];
    float* out = (float*)d_out;

    cudaFuncSetAttribute(lstm_gemm, cudaFuncAttributeMaxDynamicSharedMemorySize,
                         SMEM_BYTES);

    prep_all<<<PREP_A_BLOCKS + PREP_B_BLOCKS, 256>>>(x, h, Wx, Wh);
    dim3 grid(NTOT / BN, BATCH / BM);  // (16, 256)
    lstm_gemm<<<grid, THREADS, SMEM_BYTES>>>(C, bx, bh, out);
}